// round 6
// baseline (speedup 1.0000x reference)
#include <cuda_runtime.h>

// Problem constants
#define Bv 4096
#define Dv 256
#define Rv 8
#define Kv 10
#define DL 10
#define INV_T 10.0f

// Main-kernel tiling: 2 threads per batch element (column split 50/50),
// 112 b per block * 37 blocks = 4144 >= 4096; grid (37,8)=296 blocks = 148 SMs x 2.
#define TILE_B 112
#define THREADS 224
#define PADROW 104     // floats per U_s row: 2 halves x 52 (50 real + 2 zero pad), 16B-aligned halves
#define HALF 52
#define GRIDX 37

// Scratch (device globals; no allocation allowed)
__device__ float g_xT[Dv * Bv];              // 4 MB transposed x: xT[D][b]
__device__ float g_G[Rv * Kv * DL * DL];     // 32 KB Gram matrices G[r][k][i][j]

typedef unsigned long long ull;

__device__ __forceinline__ ull pack2(float x, float y) {
    ull r; asm("mov.b64 %0, {%1, %2};" : "=l"(r) : "f"(x), "f"(y)); return r;
}
__device__ __forceinline__ void unpack2(ull v, float& x, float& y) {
    asm("mov.b64 {%0, %1}, %2;" : "=f"(x), "=f"(y) : "l"(v));
}
// d = a*b + d  (packed 2x fp32 FMA)
__device__ __forceinline__ void fma2(ull& d, ull a, ull b) {
    asm("fma.rn.f32x2 %0, %1, %2, %0;" : "+l"(d) : "l"(a), "l"(b));
}
__device__ __forceinline__ void mul2(ull& d, ull a) {
    asm("mul.rn.f32x2 %0, %0, %1;" : "+l"(d) : "l"(a));
}

// ---------------------------------------------------------------------------
// Kernel 1: transpose x[b][D] -> g_xT[D][b]   (proven; ~5.9us)
// ---------------------------------------------------------------------------
__global__ void transpose_kernel(const float* __restrict__ x) {
    __shared__ float tile[32][33];
    int bx = blockIdx.x * 32;
    int dx = blockIdx.y * 32;
    int tx = threadIdx.x, ty = threadIdx.y;  // (32, 8)
    #pragma unroll
    for (int i = ty; i < 32; i += 8)
        tile[i][tx] = x[(size_t)(bx + i) * Dv + dx + tx];
    __syncthreads();
    #pragma unroll
    for (int i = ty; i < 32; i += 8)
        g_xT[(size_t)(dx + i) * Bv + bx + tx] = tile[tx][i];
}

// ---------------------------------------------------------------------------
// Kernel 2: G[r][k] = U^T U  (10x10 per (r,k), 80 blocks)
// ---------------------------------------------------------------------------
__global__ void g_kernel(const float* __restrict__ Us) {
    __shared__ float u[Dv * DL];
    int rk = blockIdx.x;
    const float* U = Us + (size_t)rk * Dv * DL;
    for (int i = threadIdx.x; i < Dv * DL; i += blockDim.x) u[i] = U[i];
    __syncthreads();
    int t = threadIdx.x;
    if (t < DL * DL) {
        int i = t / DL, j = t - (t / DL) * DL;
        float s = 0.0f;
        #pragma unroll 8
        for (int Dd = 0; Dd < Dv; ++Dd) s += u[Dd * DL + i] * u[Dd * DL + j];
        g_G[rk * (DL * DL) + t] = s;
    }
}

// ---------------------------------------------------------------------------
// Kernel 3: fused z -> softmax -> out.
//   2 threads per b (tid&1 = column half h: cols [h*50, h*50+50)).
//   smem: U_s[256][104] (106496B) + G_s[1000] (4000B) = 110496B -> 2 blocks/SM.
// ---------------------------------------------------------------------------
#define SMEM_FLOATS (Dv * PADROW + Kv * DL * DL)

__global__ void __launch_bounds__(THREADS, 2)
main_kernel(const float* __restrict__ Us, float* __restrict__ out) {
    extern __shared__ float sm[];
    float* U_s = sm;                    // [D][104]: half h at float offset h*52 (208B, 16B-aligned)
    float* G_s = sm + Dv * PADROW;      // [k][i][j]

    const int tid = threadIdx.x;
    const int r   = blockIdx.y;
    const int h   = tid & 1;            // column half
    const int bi  = tid >> 1;
    const int b   = blockIdx.x * TILE_B + bi;
    const int bc  = (b < Bv) ? b : (Bv - 1);   // clamp for dead tail threads

    // ---- Stage U_r into smem: U_s[Dd*104 + h2*52 + cl] = U[k][Dd][dd], pad cols 50,51 = 0 ----
    const float* Ur = Us + (size_t)r * Kv * Dv * DL;
    for (int idx = tid; idx < Dv * PADROW; idx += THREADS) {
        int Dd = idx / PADROW;
        int c  = idx - Dd * PADROW;
        int h2 = (c >= HALF) ? 1 : 0;
        int cl = c - h2 * HALF;
        float v = 0.0f;
        if (cl < 50) {
            int col = h2 * 50 + cl;
            int k   = col / DL;
            int dd  = col - k * DL;
            v = Ur[(size_t)k * (Dv * DL) + Dd * DL + dd];
        }
        U_s[idx] = v;
    }
    for (int idx = tid; idx < Kv * DL * DL; idx += THREADS)
        G_s[idx] = g_G[r * (Kv * DL * DL) + idx];
    __syncthreads();

    // ---- Phase 1: z[c] = sum_D x[b][D] * U[D][c], 26 packed accumulators (52 floats) ----
    ull z2[26];
    #pragma unroll
    for (int p = 0; p < 26; ++p) z2[p] = 0ull;

    const float* xcol = g_xT + bc;
    float xv = xcol[0];
    for (int Dd = 0; Dd < Dv; ++Dd) {
        float xn = (Dd + 1 < Dv) ? xcol[(size_t)(Dd + 1) * Bv] : 0.0f;
        ull xp = pack2(xv, xv);
        const longlong2* Urow = (const longlong2*)(U_s + Dd * PADROW) + h * 13;
        #pragma unroll
        for (int p = 0; p < 13; ++p) {
            longlong2 v = Urow[p];               // LDS.128 (broadcast per half)
            fma2(z2[2 * p],     xp, (ull)v.x);
            fma2(z2[2 * p + 1], xp, (ull)v.y);
        }
        xv = xn;
    }

    // ---- Softmax over k (thread owns 5 k's; partner via shfl_xor 1) ----
    float logit[5];
    #pragma unroll
    for (int kk = 0; kk < 5; ++kk) {
        float zk[10];
        #pragma unroll
        for (int p = 0; p < 5; ++p) unpack2(z2[kk * 5 + p], zk[2 * p], zk[2 * p + 1]);
        float nz = 0.0f;
        #pragma unroll
        for (int i = 0; i < 10; ++i) nz += zk[i] * zk[i];
        const float* Gk = G_s + (h * 5 + kk) * (DL * DL);
        float q = 0.0f;
        #pragma unroll
        for (int i = 0; i < 10; ++i) {
            float t = 0.0f;
            #pragma unroll
            for (int j = 0; j < 10; ++j) t += Gk[i * DL + j] * zk[j];
            q += zk[i] * t;
        }
        logit[kk] = (nz - 0.5f * q) * INV_T;
    }
    float mx = logit[0];
    #pragma unroll
    for (int kk = 1; kk < 5; ++kk) mx = fmaxf(mx, logit[kk]);
    mx = fmaxf(mx, __shfl_xor_sync(0xFFFFFFFFu, mx, 1));
    float e[5], se = 0.0f;
    #pragma unroll
    for (int kk = 0; kk < 5; ++kk) { e[kk] = __expf(logit[kk] - mx); se += e[kk]; }
    se += __shfl_xor_sync(0xFFFFFFFFu, se, 1);
    float inv = 1.0f / se;
    #pragma unroll
    for (int kk = 0; kk < 5; ++kk) {
        float ck = e[kk] * inv;
        ull c2 = pack2(ck, ck);
        #pragma unroll
        for (int p = 0; p < 5; ++p) mul2(z2[kk * 5 + p], c2);
    }
    // z2[25] (padding pair) accumulated only zeros -> stays 0; safe in phase 2.

    // ---- Phase 2: out[r][b][D] = sum_c w[c] U[D][c]; partner partials via shfl; f4 stores ----
    float* dst_base = out + ((size_t)r * Bv + (size_t)b) * Dv;
    for (int Dc = 0; Dc < Dv; Dc += 8) {
        float accs[8];
        #pragma unroll
        for (int j = 0; j < 8; ++j) {
            ull a0 = 0ull, a1 = 0ull;
            const longlong2* Urow = (const longlong2*)(U_s + (Dc + j) * PADROW) + h * 13;
            #pragma unroll
            for (int p = 0; p < 13; ++p) {
                longlong2 v = Urow[p];
                fma2(a0, z2[2 * p],     (ull)v.x);
                fma2(a1, z2[2 * p + 1], (ull)v.y);
            }
            float l0, h0, l1, h1;
            unpack2(a0, l0, h0);
            unpack2(a1, l1, h1);
            accs[j] = (l0 + h0) + (l1 + h1);
        }
        #pragma unroll
        for (int j = 0; j < 8; ++j)
            accs[j] += __shfl_xor_sync(0xFFFFFFFFu, accs[j], 1);
        int ci = Dc >> 3;
        if ((((ci ^ h) & 1) == 0) && (b < Bv)) {   // h=0 stores even 8-chunks, h=1 odd
            float4* dst = (float4*)(dst_base + Dc);
            dst[0] = make_float4(accs[0], accs[1], accs[2], accs[3]);
            dst[1] = make_float4(accs[4], accs[5], accs[6], accs[7]);
        }
    }
}

// ---------------------------------------------------------------------------
extern "C" void kernel_launch(void* const* d_in, const int* in_sizes, int n_in,
                              void* d_out, int out_size) {
    const float* x  = (const float*)d_in[0];   // (B, D) fp32
    const float* Us = (const float*)d_in[1];   // (R, K, D, DL) fp32
    float* out = (float*)d_out;                // (R, B, D) fp32

    cudaFuncSetAttribute(main_kernel, cudaFuncAttributeMaxDynamicSharedMemorySize,
                         SMEM_FLOATS * (int)sizeof(float));

    transpose_kernel<<<dim3(Bv / 32, Dv / 32), dim3(32, 8)>>>(x);
    g_kernel<<<Rv * Kv, 128>>>(Us);
    main_kernel<<<dim3(GRIDX, Rv), THREADS, SMEM_FLOATS * (int)sizeof(float)>>>(Us, out);
}